// round 8
// baseline (speedup 1.0000x reference)
#include <cuda_runtime.h>

#define HBV   20
#define DV    40
#define WPAD  28            // padded weight row: 112B, float4-aligned
#define EPB   16            // elements per block
#define NTHR  320           // 16 elements * 20 columns
#define JJS   404           // jj element stride (floats): bank-disjoint across elems

// Branchless fast tanh: 1 - 2/(e^{2x}+1). ~1e-6 rel err, handles +-inf limits.
__device__ __forceinline__ float tanh_fast(float x) {
    float h = __expf(2.0f * x);
    return 1.0f - __fdividef(2.0f, h + 1.0f);
}

__global__ __launch_bounds__(NTHR, 4)
void ende_kernel(const float* __restrict__ x,
                 const float* __restrict__ w1g,
                 const float* __restrict__ w2g,
                 const float* __restrict__ w3g,
                 const float* __restrict__ w4g,
                 float* __restrict__ out_vec,
                 float* __restrict__ out_jt)
{
    __shared__ __align__(16) float  sw1[HBV * WPAD];
    __shared__ __align__(16) float  sw2[HBV * WPAD];
    __shared__ __align__(16) float  sw3[HBV * WPAD];
    __shared__ __align__(16) float  sw4[HBV * WPAD];
    __shared__ __align__(16) float4 cw4[HBV * HBV];  // (w1,w2,w3,w4)[k][c]
    __shared__ __align__(16) float  p1s[EPB][HBV];
    __shared__ __align__(16) float  s2s[EPB][HBV];
    __shared__ __align__(16) float4 cfs[EPB][HBV];   // (b1,b2,a3,a4) per row k
    __shared__ __align__(16) float  jjs[EPB * JJS];  // JJ12 per element

    const int tid = threadIdx.x;

    // Stage weights into padded smem + fused float4 copy (once per block)
    for (int idx = tid; idx < HBV * HBV; idx += NTHR) {
        int r = idx / HBV, cc = idx % HBV;
        float v1 = w1g[idx], v2 = w2g[idx], v3 = w3g[idx], v4 = w4g[idx];
        sw1[r * WPAD + cc] = v1;
        sw2[r * WPAD + cc] = v2;
        sw3[r * WPAD + cc] = v3;
        sw4[r * WPAD + cc] = v4;
        cw4[idx] = make_float4(v1, v2, v3, v4);
    }

    const int e = tid / HBV;          // element slot within block
    const int c = tid - e * HBV;      // column / row index owned by this lane
    const long long b = (long long)blockIdx.x * EPB + e;

    // ---- load x; publish p1 vector ----
    const float p1_own = x[b * DV + c];
    const float p2_own = x[b * DV + HBV + c];
    p1s[e][c] = p1_own;
    __syncthreads();

    // ---- Stage A: lane -> f1[c], f2[c] of element e (row-c matvec) ----
    float e2_own, s2_own;
    {
        float a1 = 0.f, a2 = 0.f;
        const float4* r1 = (const float4*)(sw1 + c * WPAD);
        const float4* r2 = (const float4*)(sw2 + c * WPAD);
        const float4* pv = (const float4*)(p1s[e]);
        #pragma unroll
        for (int g = 0; g < 5; g++) {
            float4 A = r1[g], Bv = r2[g], P = pv[g];
            a1 = fmaf(A.x,  P.x, a1); a1 = fmaf(A.y,  P.y, a1);
            a1 = fmaf(A.z,  P.z, a1); a1 = fmaf(A.w,  P.w, a1);
            a2 = fmaf(Bv.x, P.x, a2); a2 = fmaf(Bv.y, P.y, a2);
            a2 = fmaf(Bv.z, P.z, a2); a2 = fmaf(Bv.w, P.w, a2);
        }
        float f1 = tanh_fast(a1);
        float f2 = tanh_fast(a2);
        e2_own = __expf(f2);
        float p2e = p2_own * e2_own;
        s2_own = p2e + f1;
        s2s[e][c] = s2_own;
        ((float2*)&cfs[e][c])[0] = make_float2(1.f - f1 * f1,
                                               p2e * (1.f - f2 * f2));
    }
    __syncthreads();

    // ---- Stage B: lane -> f3[c], f4[c]; out vector ----
    float e4_own;
    {
        float a3 = 0.f, a4 = 0.f;
        const float4* r3 = (const float4*)(sw3 + c * WPAD);
        const float4* r4 = (const float4*)(sw4 + c * WPAD);
        const float4* sv = (const float4*)(s2s[e]);
        #pragma unroll
        for (int g = 0; g < 5; g++) {
            float4 A = r3[g], Bv = r4[g], S = sv[g];
            a3 = fmaf(A.x,  S.x, a3); a3 = fmaf(A.y,  S.y, a3);
            a3 = fmaf(A.z,  S.z, a3); a3 = fmaf(A.w,  S.w, a3);
            a4 = fmaf(Bv.x, S.x, a4); a4 = fmaf(Bv.y, S.y, a4);
            a4 = fmaf(Bv.z, S.z, a4); a4 = fmaf(Bv.w, S.w, a4);
        }
        float f3 = tanh_fast(a3);
        float f4 = tanh_fast(a4);
        e4_own = __expf(f4);
        float s1e = p1_own * e4_own;
        ((float2*)&cfs[e][c])[1] = make_float2(1.f - f3 * f3,
                                               s1e * (1.f - f4 * f4));
        out_vec[b * DV + c]       = s1e + f3;
        out_vec[b * DV + HBV + c] = s2_own;
    }
    __syncthreads();

    float* jt = out_jt + b * (DV * DV);
    float* jje = jjs + e * JJS;

    // ---- Fused loop over k: J21 row k -> regs + BL; BR; JJ12 row k -> smem + TR ----
    float J21r[HBV];
    #pragma unroll
    for (int k = 0; k < HBV; k++) {
        float4 cf = cfs[e][k];             // per-element broadcast
        float4 wv = cw4[k * HBV + c];      // (w1,w2,w3,w4) one LDS.128

        float v = fmaf(cf.x, wv.x, cf.y * wv.y);   // J21[k, c]
        J21r[k] = v;
        jt[(HBV + k) * DV + c]       = v;
        jt[(HBV + k) * DV + HBV + c] = (c == k) ? e2_own : 0.f;

        float u = fmaf(cf.z, wv.z, cf.w * wv.w);   // JJ12[k, c]
        jje[k * HBV + c]       = u;
        jt[k * DV + HBV + c]   = u * e2_own;       // TR = JJ12 * diag(e2)
    }
    __syncthreads();

    // ---- Top-left: TL[i, c] = e4[i] delta_ic + sum_k JJ12[i,k] * J21[k,c] ----
    #pragma unroll 4
    for (int i = 0; i < HBV; i++) {
        const float4* rv = (const float4*)(jje + i * HBV);   // row broadcast
        float m = 0.f;
        #pragma unroll
        for (int g = 0; g < 5; g++) {
            float4 r = rv[g];
            m = fmaf(r.x, J21r[4 * g + 0], m);
            m = fmaf(r.y, J21r[4 * g + 1], m);
            m = fmaf(r.z, J21r[4 * g + 2], m);
            m = fmaf(r.w, J21r[4 * g + 3], m);
        }
        if (i == c) m += e4_own;
        jt[i * DV + c] = m;
    }
}

extern "C" void kernel_launch(void* const* d_in, const int* in_sizes, int n_in,
                              void* d_out, int out_size) {
    const float* x  = (const float*)d_in[0];
    const float* w1 = (const float*)d_in[1];
    const float* w2 = (const float*)d_in[2];
    const float* w3 = (const float*)d_in[3];
    const float* w4 = (const float*)d_in[4];

    const int B = in_sizes[0] / DV;            // 65536
    float* out_vec = (float*)d_out;            // tuple element 0: (B,1,40)
    float* out_jt  = out_vec + (size_t)B * DV; // tuple element 1: (B,40,40)

    ende_kernel<<<B / EPB, NTHR>>>(x, w1, w2, w3, w4, out_vec, out_jt);
}